// round 12
// baseline (speedup 1.0000x reference)
#include <cuda_runtime.h>
#include <cooperative_groups.h>

namespace cg = cooperative_groups;

typedef unsigned long long u64;

// Problem constants (fixed by the benchmark)
#define BATCH  512
#define TLEN   1024
#define DDIM   64
#define UDIM   128
#define ROWS   8          // batch rows per cluster
#define NTHR   256        // 8 warps; k-half split IN-WARP (lanes 0-15 vs 16-31)
#define WSTRIDE 196       // 192 k-values + 4 pad words (conflict-free 16B lane stride)

// Shared memory layout (floats)
//   Wsm  : 256 cols * 196 = 50176   @0
//   bsm  : 256                      @50176
//   zbuf : 2 * 8 * 192 = 3072       @50432   (per row: [x(64) | h(128)], double-buffered)
// total 53504 floats = 214016 bytes
#define OFF_B 50176
#define OFF_Z 50432
#define ZROW  192         // floats per z row
#define ZPAR  1536        // floats per parity buffer (8 rows * 192)
#define SMEM_FLOATS 53504
#define SMEM_BYTES  (SMEM_FLOATS * 4)

#define CLUSTER_ARRIVE() asm volatile("barrier.cluster.arrive.aligned;" ::: "memory")
#define CLUSTER_WAIT()   asm volatile("barrier.cluster.wait.aligned;"   ::: "memory")

__device__ __forceinline__ float sigf(float x) {
    return 1.0f / (1.0f + __expf(-x));
}
__device__ __forceinline__ float tanhf_fast(float x) {
    return 1.0f - 2.0f / (1.0f + __expf(2.0f * x));
}

// ---- packed f32x2 helpers (PTX-only; ptxas never auto-fuses FFMA2) ----
__device__ __forceinline__ void fma2(u64& acc, u64 a, u64 b) {
    asm("fma.rn.f32x2 %0, %1, %2, %0;" : "+l"(acc) : "l"(a), "l"(b));
}
__device__ __forceinline__ u64 pack2(float lo, float hi) {
    u64 r;
    asm("mov.b64 %0, {%1, %2};" : "=l"(r) : "f"(lo), "f"(hi));
    return r;
}
__device__ __forceinline__ float fold2(u64 v) {
    float lo, hi;
    asm("mov.b64 {%0, %1}, %2;" : "=f"(lo), "=f"(hi) : "l"(v));
    return lo + hi;
}

extern __shared__ float smem[];

__global__ void __launch_bounds__(NTHR, 1) __cluster_dims__(2, 1, 1)
lstm_persistent_kernel(
    const float* __restrict__ x,
    const float* __restrict__ Wf, const float* __restrict__ Uf, const float* __restrict__ bf,
    const float* __restrict__ Wi, const float* __restrict__ Ui, const float* __restrict__ bi,
    const float* __restrict__ Wc, const float* __restrict__ Uc, const float* __restrict__ bc,
    const float* __restrict__ Wo, const float* __restrict__ Uo, const float* __restrict__ bo,
    float* __restrict__ out)
{
    float* Wsm  = smem;
    float* bsm  = smem + OFF_B;
    float* zbuf = smem + OFF_Z;

    cg::cluster_group cluster = cg::this_cluster();
    const int q   = (int)cluster.block_rank();     // 0/1: which 64-col half of U this CTA owns
    const int tid = threadIdx.x;
    const int b0  = (blockIdx.x >> 1) * ROWS;      // batch-row base for this cluster

    float* zbuf_peer = cluster.map_shared_rank(zbuf, q ^ 1);

    // ---- one-time: weights into smem, column-major [col][k], col = gate*64 + uu ----
    // k-layout per column: k 0..63 = x weights, k 64..191 = h weights (matches zbuf rows)
    const float* Wg[4] = {Wf, Wi, Wc, Wo};
    const float* Ug[4] = {Uf, Ui, Uc, Uo};
    const float* bg[4] = {bf, bi, bc, bo};

    #pragma unroll
    for (int g = 0; g < 4; g++) {
        for (int idx = tid; idx < 64 * 64; idx += NTHR) {
            int d  = idx >> 6;
            int u2 = idx & 63;
            Wsm[(g * 64 + u2) * WSTRIDE + d] = Wg[g][d * UDIM + q * 64 + u2];
        }
        for (int idx = tid; idx < 128 * 64; idx += NTHR) {
            int kk = idx >> 6;
            int u2 = idx & 63;
            Wsm[(g * 64 + u2) * WSTRIDE + 64 + kk] = Ug[g][kk * UDIM + q * 64 + u2];
        }
        if (tid < 64) bsm[g * 64 + tid] = bg[g][q * 64 + tid];
    }

    // zero zbuf (both parities), then load x_{t=0} into parity-0 x slots
    for (int idx = tid; idx < 2 * ZPAR; idx += NTHR) zbuf[idx] = 0.0f;
    __syncthreads();
    {
        int r0 = tid >> 6, d0 = tid & 63;
        zbuf[r0 * ZROW + d0]       = x[(b0 + r0)     * (TLEN * DDIM) + d0];
        zbuf[(r0 + 4) * ZROW + d0] = x[(b0 + r0 + 4) * (TLEN * DDIM) + d0];
    }
    __syncthreads();

    // ---- thread ownership: (uu, 4-row group, in-warp k-half) ----
    const int lane  = tid & 31;
    const int warp  = tid >> 5;
    const int kh    = lane >> 4;                   // k-half: lanes 0-15 vs 16-31
    const int uu    = (warp & 3) * 16 + (lane & 15);   // [0,64)
    const int rbase = (warp >> 2) * 4;             // rows rbase..rbase+3

    const ulonglong2* Wc0 = (const ulonglong2*)(Wsm + (uu      ) * WSTRIDE);  // gate f
    const ulonglong2* Wc1 = (const ulonglong2*)(Wsm + (uu +  64) * WSTRIDE);  // gate i
    const ulonglong2* Wc2 = (const ulonglong2*)(Wsm + (uu + 128) * WSTRIDE);  // gate c
    const ulonglong2* Wc3 = (const ulonglong2*)(Wsm + (uu + 192) * WSTRIDE);  // gate o

    // u2-slice bases (48 u2 per column: x = 0..15, h = 16..47; h m-index = u2-16)
    //   local h  : m in [q*16, q*16+16)  — produced by this CTA, ordered by syncthreads
    //   peer  h  : m in [(q^1)*16, ...)  — pushed by peer, needs CLUSTER_WAIT
    // balanced split: kh=0 pre: x(16) / kh=1 pre: local h(16); each kh: 8 peer u2 post-wait
    const int mloc   = q * 16;
    const int mpeer  = (q ^ 1) * 16;
    const int s_pre  = kh ? (16 + mloc) : 0;
    const int s_post = 16 + mpeer + kh * 8;

    // bias only in kh=0 partials (reduction would double it otherwise)
    const u64 bp0 = kh ? 0ull : pack2(bsm[uu      ], 0.0f);
    const u64 bp1 = kh ? 0ull : pack2(bsm[uu +  64], 0.0f);
    const u64 bp2 = kh ? 0ull : pack2(bsm[uu + 128], 0.0f);
    const u64 bp3 = kh ? 0ull : pack2(bsm[uu + 192], 0.0f);

    // this thread's 2 state cells: rows rbase + kh*2 + {0,1}, column q*64+uu
    float cs0 = 0.0f, cs1 = 0.0f;     // c state (registers; csm eliminated)
    float h0  = 0.0f, h1  = 0.0f;     // last h (for final output)
    const int rA = rbase + kh * 2;

    // x-prefetch mapping (coalesced)
    const int pr = tid >> 6, pd = tid & 63;

    CLUSTER_ARRIVE();   // seed arrive/wait pipeline (matches step-0 wait)

    for (int t = 0; t < TLEN; t++) {
        const int p = t & 1;

        // ---- prefetch x_{t+1} into registers (overlaps the whole FMA phase) ----
        float pf0 = 0.0f, pf1 = 0.0f;
        if (t + 1 < TLEN) {
            pf0 = x[(b0 + pr)     * (TLEN * DDIM) + (t + 1) * DDIM + pd];
            pf1 = x[(b0 + pr + 4) * (TLEN * DDIM) + (t + 1) * DDIM + pd];
        }

        // acc[g][r]: gate g, row rbase+r, this thread's k-half partial (f32x2 packed)
        u64 acc[4][4];
        #pragma unroll
        for (int r = 0; r < 4; r++) {
            acc[0][r] = bp0; acc[1][r] = bp1; acc[2][r] = bp2; acc[3][r] = bp3;
        }

        const ulonglong2* zp = (const ulonglong2*)(zbuf + p * ZPAR);  // [8 rows][48 u2]

        // ---- pre-wait slices: kh=0 -> x, kh=1 -> local h (same body, base differs) ----
        #pragma unroll 8
        for (int i = 0; i < 16; i++) {
            int s = s_pre + i;
            ulonglong2 w0 = Wc0[s], w1 = Wc1[s], w2 = Wc2[s], w3 = Wc3[s];
            #pragma unroll
            for (int r = 0; r < 4; r++) {
                ulonglong2 v = zp[(rbase + r) * 48 + s];   // 2-addr broadcast
                fma2(acc[0][r], v.x, w0.x); fma2(acc[0][r], v.y, w0.y);
                fma2(acc[1][r], v.x, w1.x); fma2(acc[1][r], v.y, w1.y);
                fma2(acc[2][r], v.x, w2.x); fma2(acc[2][r], v.y, w2.y);
                fma2(acc[3][r], v.x, w3.x); fma2(acc[3][r], v.y, w3.y);
            }
        }

        // ---- peer-pushed h half: visible after acquire ----
        CLUSTER_WAIT();

        #pragma unroll 8
        for (int i = 0; i < 8; i++) {
            int s = s_post + i;
            ulonglong2 w0 = Wc0[s], w1 = Wc1[s], w2 = Wc2[s], w3 = Wc3[s];
            #pragma unroll
            for (int r = 0; r < 4; r++) {
                ulonglong2 v = zp[(rbase + r) * 48 + s];
                fma2(acc[0][r], v.x, w0.x); fma2(acc[0][r], v.y, w0.y);
                fma2(acc[1][r], v.x, w1.x); fma2(acc[1][r], v.y, w1.y);
                fma2(acc[2][r], v.x, w2.x); fma2(acc[2][r], v.y, w2.y);
                fma2(acc[3][r], v.x, w3.x); fma2(acc[3][r], v.y, w3.y);
            }
        }

        // ---- in-warp k-half reduction: send partner's rows, receive mine ----
        float s0[4], s1[4];   // full gate preactivations for my 2 rows
        #pragma unroll
        for (int g = 0; g < 4; g++) {
            float fA = fold2(acc[g][0]), fB = fold2(acc[g][1]);
            float fC = fold2(acc[g][2]), fD = fold2(acc[g][3]);
            float own0 = kh ? fC : fA;
            float own1 = kh ? fD : fB;
            float oth0 = kh ? fA : fC;    // partial for partner's first row
            float oth1 = kh ? fB : fD;
            s0[g] = own0 + __shfl_xor_sync(0xffffffffu, oth0, 16);
            s1[g] = own1 + __shfl_xor_sync(0xffffffffu, oth1, 16);
        }

        // ---- gate math in registers; push h to self AND peer ----
        float* zl = zbuf      + (p ^ 1) * ZPAR + 64 + q * 64 + uu;
        float* zq = zbuf_peer + (p ^ 1) * ZPAR + 64 + q * 64 + uu;
        {
            float cn = fmaf(sigf(s0[0]), cs0, sigf(s0[1]) * tanhf_fast(s0[2]));
            cs0 = cn;
            h0 = sigf(s0[3]) * tanhf_fast(cn);
            zl[rA * ZROW] = h0;
            zq[rA * ZROW] = h0;            // DSMEM push to peer
        }
        {
            float cn = fmaf(sigf(s1[0]), cs1, sigf(s1[1]) * tanhf_fast(s1[2]));
            cs1 = cn;
            h1 = sigf(s1[3]) * tanhf_fast(cn);
            zl[(rA + 1) * ZROW] = h1;
            zq[(rA + 1) * ZROW] = h1;
        }

        // stash the x prefetch for step t+1 (other parity buffer)
        if (t + 1 < TLEN) {
            zbuf[(p ^ 1) * ZPAR + pr * ZROW + pd]       = pf0;
            zbuf[(p ^ 1) * ZPAR + (pr + 4) * ZROW + pd] = pf1;
        }

        __syncthreads();     // local h + x stash ordered for next step's readers
        CLUSTER_ARRIVE();    // release: peer pushes published; wait deferred into t+1
    }

    // final h of this thread's 2 cells is in registers
    out[(b0 + rA)     * UDIM + q * 64 + uu] = h0;
    out[(b0 + rA + 1) * UDIM + q * 64 + uu] = h1;

    CLUSTER_WAIT();   // drain final arrives; peer done touching our smem before exit
}

extern "C" void kernel_launch(void* const* d_in, const int* in_sizes, int n_in,
                              void* d_out, int out_size)
{
    const float* x  = (const float*)d_in[0];
    const float* Wf = (const float*)d_in[1];
    const float* Uf = (const float*)d_in[2];
    const float* bf = (const float*)d_in[3];
    const float* Wi = (const float*)d_in[4];
    const float* Ui = (const float*)d_in[5];
    const float* bi = (const float*)d_in[6];
    const float* Wc = (const float*)d_in[7];
    const float* Uc = (const float*)d_in[8];
    const float* bc = (const float*)d_in[9];
    const float* Wo = (const float*)d_in[10];
    const float* Uo = (const float*)d_in[11];
    const float* bo = (const float*)d_in[12];
    float* out = (float*)d_out;

    cudaFuncSetAttribute(lstm_persistent_kernel,
                         cudaFuncAttributeMaxDynamicSharedMemorySize, SMEM_BYTES);

    // 64 clusters x 2 CTAs = 128 CTAs; each cluster owns 8 batch rows.
    lstm_persistent_kernel<<<128, NTHR, SMEM_BYTES>>>(
        x, Wf, Uf, bf, Wi, Ui, bi, Wc, Uc, bc, Wo, Uo, bo, out);
}

// round 13
// speedup vs baseline: 1.7884x; 1.7884x over previous
#include <cuda_runtime.h>
#include <cooperative_groups.h>

namespace cg = cooperative_groups;

typedef unsigned long long u64;

// Problem constants (fixed by the benchmark)
#define BATCH  512
#define TLEN   1024
#define DDIM   64
#define UDIM   128
#define ROWS   8          // batch rows per cluster
#define NTHR   256        // 8 warps; k-split across two 128-thread halves (NOT in-warp)
#define WSTRIDE 196       // 192 k-values + 4 pad words (conflict-free: 196 % 32 == 4)

// Shared memory layout (floats)
//   Wsm   : 256 cols * 196          = 50176
//   h_buf : 2 * 8 * 128 = 2048      -> @50176
//   x_buf : 2 * 8 * 64  = 1024      -> @52224
//   c_sm  : 512                     -> @53248
//   g_sm  : 2 * 2048 = 4096         -> @53760   (two partial banks, one per k-half)
//   bias  : 256 (ALIASES g_sm; consumed into regs before first g_sm write)
// total 57856 floats = 231424 bytes (<= 232448 opt-in cap)
#define OFF_H    50176
#define OFF_X    52224
#define OFF_C    53248
#define OFF_G    53760
#define OFF_BIAS OFF_G
#define SMEM_FLOATS 57856
#define SMEM_BYTES  (SMEM_FLOATS * 4)

// Split cluster barrier: arrive (release) at end of combine, wait (acquire)
// deferred until the peer-h part of the NEXT step's FMA phase.
#define CLUSTER_ARRIVE() asm volatile("barrier.cluster.arrive.aligned;" ::: "memory")
#define CLUSTER_WAIT()   asm volatile("barrier.cluster.wait.aligned;"   ::: "memory")

// Fast activations: MUFU rcp via __fdividef (no slow div.rn refinement sequence).
// Error ~1e-7 relative — noise against the 1e-3 threshold.
__device__ __forceinline__ float sigf(float x) {
    return __fdividef(1.0f, 1.0f + __expf(-x));
}
__device__ __forceinline__ float tanhf_fast(float x) {
    // tanh(x) = 1 - 2/(1 + e^{2x}); stable for large |x|
    return 1.0f - __fdividef(2.0f, 1.0f + __expf(2.0f * x));
}

// ---- packed f32x2 helpers (PTX-only; ptxas never auto-fuses FFMA2) ----
__device__ __forceinline__ void fma2(u64& acc, u64 a, u64 b) {
    asm("fma.rn.f32x2 %0, %1, %2, %0;" : "+l"(acc) : "l"(a), "l"(b));
}
__device__ __forceinline__ u64 pack2(float lo, float hi) {
    u64 r;
    asm("mov.b64 %0, {%1, %2};" : "=l"(r) : "f"(lo), "f"(hi));
    return r;
}
__device__ __forceinline__ float fold2(u64 v) {
    float lo, hi;
    asm("mov.b64 {%0, %1}, %2;" : "=f"(lo), "=f"(hi) : "l"(v));
    return lo + hi;
}

extern __shared__ float smem[];

__global__ void __launch_bounds__(NTHR, 1) __cluster_dims__(2, 1, 1)
lstm_persistent_kernel(
    const float* __restrict__ x,
    const float* __restrict__ Wf, const float* __restrict__ Uf, const float* __restrict__ bf,
    const float* __restrict__ Wi, const float* __restrict__ Ui, const float* __restrict__ bi,
    const float* __restrict__ Wc, const float* __restrict__ Uc, const float* __restrict__ bc,
    const float* __restrict__ Wo, const float* __restrict__ Uo, const float* __restrict__ bo,
    float* __restrict__ out)
{
    float* Wsm  = smem;
    float* hbuf = smem + OFF_H;
    float* xbuf = smem + OFF_X;
    float* csm  = smem + OFF_C;
    float* gsm  = smem + OFF_G;
    float* bsm  = smem + OFF_BIAS;   // aliases gsm; valid only until first gsm write

    cg::cluster_group cluster = cg::this_cluster();
    const int q   = (int)cluster.block_rank();     // 0/1: which 64-col half of U this CTA owns
    const int tid = threadIdx.x;
    const int b0  = (blockIdx.x >> 1) * ROWS;      // batch-row base for this cluster

    float* hbuf_peer = cluster.map_shared_rank(hbuf, q ^ 1);

    // ---- one-time: weights into smem, column-major [col][k], col = gate*64 + uu ----
    const float* Wg[4] = {Wf, Wi, Wc, Wo};
    const float* Ug[4] = {Uf, Ui, Uc, Uo};
    const float* bg[4] = {bf, bi, bc, bo};

    #pragma unroll
    for (int g = 0; g < 4; g++) {
        for (int idx = tid; idx < 64 * 64; idx += NTHR) {
            int d  = idx >> 6;
            int uu = idx & 63;
            Wsm[(g * 64 + uu) * WSTRIDE + d] = Wg[g][d * UDIM + q * 64 + uu];
        }
        for (int idx = tid; idx < 128 * 64; idx += NTHR) {
            int kk = idx >> 6;
            int uu = idx & 63;
            Wsm[(g * 64 + uu) * WSTRIDE + 64 + kk] = Ug[g][kk * UDIM + q * 64 + uu];
        }
        if (tid < 64) bsm[g * 64 + tid] = bg[g][q * 64 + tid];
    }

    for (int idx = tid; idx < 2048; idx += NTHR) hbuf[idx] = 0.0f;
    for (int idx = tid; idx < 512;  idx += NTHR) csm[idx]  = 0.0f;

    // preload x_{t=0}: 512 floats, 2 per thread
    #pragma unroll
    for (int i = 0; i < 2; i++) {
        int idx = tid + i * NTHR;
        int r = idx >> 6, d = idx & 63;
        xbuf[idx] = x[(b0 + r) * (TLEN * DDIM) + d];
    }
    __syncthreads();

    // k-split ownership (cross-WARP halves; operand broadcasts stay 1-address/warp):
    //   half = tid>>7; thread covers cols c0 = tid&127 (gates f/i) and c1 = c0+128
    //   (gates c/o), 8 rows each, over 24 k4-slices:
    //     x slice      : j  = half*8      + jj,  jj=0..7   (k 0..63, no dependency)
    //     local-h slice: m  = q*16+half*8 + jj             (h produced by THIS CTA)
    //     peer-h slice : m' = (q^1)*16+half*8 + jj         (h pushed by peer -> after wait)
    const int    half = tid >> 7;
    const int    ct   = tid & 127;
    const int    c0   = ct;
    const int    c1   = ct + 128;
    const ulonglong2* W20 = (const ulonglong2*)(Wsm + c0 * WSTRIDE);
    const ulonglong2* W21 = (const ulonglong2*)(Wsm + c1 * WSTRIDE);
    const int    xbase = half * 8;
    const int    mloc  = q * 16 + half * 8;
    const int    mpeer = (q ^ 1) * 16 + half * 8;
    const int    uu   = ct & 63;
    const int    g0   = ct >> 6;                 // 0 or 1
    const int    pb   = half * 2048;             // partial bank
    const int    gidx0 = pb + g0 * 512 + uu;
    const int    gidx1 = pb + (g0 + 2) * 512 + uu;
    // bias goes only into half 0's partials (bsm aliases gsm -> consume now, then barrier)
    const u64    bp0  = (half == 0) ? pack2(bsm[c0], 0.0f) : 0ull;
    const u64    bp1  = (half == 0) ? pack2(bsm[c1], 0.0f) : 0ull;
    __syncthreads();   // all bias reads complete before first gsm write

    CLUSTER_ARRIVE();  // seed the arrive/wait pipeline (matches step-0 wait)

    for (int t = 0; t < TLEN; t++) {
        const int p = t & 1;

        // ---- prefetch x_{t+1} into registers (overlaps with whole FMA phase) ----
        float pf0 = 0.0f, pf1 = 0.0f;
        if (t + 1 < TLEN) {
            int r1 = tid >> 6, d1 = tid & 63;          // idx = tid
            pf0 = x[(b0 + r1)     * (TLEN * DDIM) + (t + 1) * DDIM + d1];
            pf1 = x[(b0 + r1 + 4) * (TLEN * DDIM) + (t + 1) * DDIM + d1];  // idx = tid+256
        }

        u64 a0[8], a1[8];
        #pragma unroll
        for (int r = 0; r < 8; r++) { a0[r] = bp0; a1[r] = bp1; }

        const ulonglong2* xb = (const ulonglong2*)(xbuf + p * 512);    // [8][16]
        const ulonglong2* hb = (const ulonglong2*)(hbuf + p * 1024);   // [8][32]

        // ---- x part (no recurrent dependency) ----
        #pragma unroll
        for (int jj = 0; jj < 8; jj++) {
            int j = xbase + jj;
            ulonglong2 w0 = W20[j];
            ulonglong2 w1 = W21[j];
            #pragma unroll
            for (int r = 0; r < 8; r++) {
                ulonglong2 v = xb[r * 16 + j];        // warp-uniform broadcast
                fma2(a0[r], v.x, w0.x);
                fma2(a0[r], v.y, w0.y);
                fma2(a1[r], v.x, w1.x);
                fma2(a1[r], v.y, w1.y);
            }
        }

        // ---- locally-produced h half (ordered by last step's B2 syncthreads) ----
        #pragma unroll
        for (int jj = 0; jj < 8; jj++) {
            int m = mloc + jj;
            ulonglong2 w0 = W20[16 + m];
            ulonglong2 w1 = W21[16 + m];
            #pragma unroll
            for (int r = 0; r < 8; r++) {
                ulonglong2 v = hb[r * 32 + m];
                fma2(a0[r], v.x, w0.x);
                fma2(a0[r], v.y, w0.y);
                fma2(a1[r], v.x, w1.x);
                fma2(a1[r], v.y, w1.y);
            }
        }

        // ---- now (and only now) we need the peer's pushed h half ----
        CLUSTER_WAIT();   // acquire: peer's DSMEM h stores of step t-1 visible

        #pragma unroll
        for (int jj = 0; jj < 8; jj++) {
            int m = mpeer + jj;
            ulonglong2 w0 = W20[16 + m];
            ulonglong2 w1 = W21[16 + m];
            #pragma unroll
            for (int r = 0; r < 8; r++) {
                ulonglong2 v = hb[r * 32 + m];
                fma2(a0[r], v.x, w0.x);
                fma2(a0[r], v.y, w0.y);
                fma2(a1[r], v.x, w1.x);
                fma2(a1[r], v.y, w1.y);
            }
        }

        // publish partials (fold even/odd halves)
        #pragma unroll
        for (int r = 0; r < 8; r++) {
            gsm[gidx0 + r * 64] = fold2(a0[r]);
            gsm[gidx1 + r * 64] = fold2(a1[r]);
        }
        __syncthreads();                              // B1: gsm ready

        // stash the x prefetch for step t+1 (other parity buffer)
        if (t + 1 < TLEN) {
            xbuf[(p ^ 1) * 512 + tid]       = pf0;
            xbuf[(p ^ 1) * 512 + tid + 256] = pf1;
        }

        // ---- combine k-half partials + gate math; push h-half to self AND peer ----
        float* hl = hbuf      + (p ^ 1) * 1024;
        float* hp = hbuf_peer + (p ^ 1) * 1024;
        #pragma unroll
        for (int it = 0; it < 2; it++) {
            int i = tid + it * NTHR;                  // i = r*64 + uu, 512 state cells
            float gf = gsm[i]        + gsm[2048 + i];
            float gi = gsm[512 + i]  + gsm[2560 + i];
            float gc = gsm[1024 + i] + gsm[3072 + i];
            float go = gsm[1536 + i] + gsm[3584 + i];
            float fg = sigf(gf);
            float ig = sigf(gi);
            float ctl = tanhf_fast(gc);
            float og = sigf(go);
            float cn = fmaf(fg, csm[i], ig * ctl);
            csm[i]   = cn;
            float hn = og * tanhf_fast(cn);
            int r  = i >> 6;
            int u2 = i & 63;
            hl[r * 128 + q * 64 + u2] = hn;
            hp[r * 128 + q * 64 + u2] = hn;           // DSMEM push to peer
        }
        __syncthreads();                              // B2: local h/x writes ordered

        CLUSTER_ARRIVE();  // release: our pushes to peer are published; wait deferred
    }

    CLUSTER_WAIT();        // drain final arrives; peer done touching our smem

    // final h lives in hbuf parity 0; each CTA wrote its own q-half locally
    #pragma unroll
    for (int it = 0; it < 2; it++) {
        int i  = tid + it * NTHR;
        int r  = i >> 6;
        int u2 = i & 63;
        out[(b0 + r) * UDIM + q * 64 + u2] = hbuf[r * 128 + q * 64 + u2];
    }
}

extern "C" void kernel_launch(void* const* d_in, const int* in_sizes, int n_in,
                              void* d_out, int out_size)
{
    const float* x  = (const float*)d_in[0];
    const float* Wf = (const float*)d_in[1];
    const float* Uf = (const float*)d_in[2];
    const float* bf = (const float*)d_in[3];
    const float* Wi = (const float*)d_in[4];
    const float* Ui = (const float*)d_in[5];
    const float* bi = (const float*)d_in[6];
    const float* Wc = (const float*)d_in[7];
    const float* Uc = (const float*)d_in[8];
    const float* bc = (const float*)d_in[9];
    const float* Wo = (const float*)d_in[10];
    const float* Uo = (const float*)d_in[11];
    const float* bo = (const float*)d_in[12];
    float* out = (float*)d_out;

    cudaFuncSetAttribute(lstm_persistent_kernel,
                         cudaFuncAttributeMaxDynamicSharedMemorySize, SMEM_BYTES);

    // 64 clusters x 2 CTAs = 128 CTAs; each cluster owns 8 batch rows.
    lstm_persistent_kernel<<<128, NTHR, SMEM_BYTES>>>(
        x, Wf, Uf, bf, Wi, Ui, bi, Wc, Uc, bc, Wo, Uo, bo, out);
}